// round 13
// baseline (speedup 1.0000x reference)
#include <cuda_runtime.h>
#include <cuda_bf16.h>

#define IN_DIM   512
#define BATCH    8192
#define GRID_NUM 48
#define NCOEF    (GRID_NUM + 3)   // 51
#define NKNOT    (GRID_NUM + 1)   // 49
#define TILE     64               // dims per block -> 8 dim-tiles
#define THREADS  256
#define NBLOCKS  888              // 148 SMs x 6 blocks: one wave (proven best config)
#define NRGCOL   111              // row-slot columns per dim-tile (888/8)
#define NSLOT    1024             // BATCH/8 row-slots per dim-tile
#define CELL_LO  24               // x in [0,1) -> t in [24,48)
#define NCELL_S  24
#define NCOL_S   27               // coef cols 24..50

// Cold path: recompute quad from global coef (never taken for in-range x).
__device__ __noinline__ float eval_cold(float tf, const float* __restrict__ coef, int col) {
    float t = tf + (float)CELL_LO;
    int cell = max(0, min(__float2int_rd(t), GRID_NUM - 1));
    float u = t - (float)cell;
    const float* p = coef + col * NCOEF + cell;
    float c0 = p[0], c1 = p[1], c2 = p[2], c3 = p[3];
    float ax = (c0 + 4.0f * c1 + c2) * (1.0f / 6.0f);
    float ay = (c2 - c0) * 0.5f;
    float az = (c0 - 2.0f * c1 + c2) * 0.5f;
    float aw = (c3 - c0 + 3.0f * (c1 - c2)) * (1.0f / 6.0f);
    return fmaf(fmaf(fmaf(aw, u, az), u, ay), u, ax);
}

__device__ __forceinline__ float eval_hot(float xv, float A, float B,
                                          const float4* __restrict__ tab,
                                          const float* __restrict__ coef, int col) {
    float tf = fmaf(xv, A, B);                 // t - 24
    int cs = __float2int_rd(tf);
    if (__builtin_expect((unsigned)cs < (unsigned)NCELL_S, 1)) {
        float u = tf - (float)cs;
        float4 a = tab[cs * 32];               // conflict-free LDS.128
        return fmaf(fmaf(fmaf(a.w, u, a.z), u, a.y), u, a.x);
    }
    return eval_cold(tf, coef, col);
}

__global__ __launch_bounds__(THREADS, 6) void bspline_fused_kernel(
    const float* __restrict__ x,
    const float* __restrict__ grid,
    const float* __restrict__ coef,
    float* __restrict__ y)
{
    __shared__ float4 s_e[NCELL_S * 32];       // even dims: 12 KB
    __shared__ float4 s_o[NCELL_S * 32];       // odd  dims: 12 KB
    __shared__ float  s_c[TILE * NCOL_S];      // staging:  6.75 KB

    const int tid  = threadIdx.x;
    const int bid  = blockIdx.x;
    const int dim0 = (bid & 7) * TILE;
    const int cgrp = bid >> 3;                 // 0..110 row-slot column

    // Stage coef cols 24..50 for 64 dims (contiguous 27-float runs, coalesced).
    for (int k = tid; k < TILE * NCOL_S; k += THREADS) {
        int d = k / NCOL_S, cc = k - d * NCOL_S;
        s_c[k] = coef[(dim0 + d) * NCOEF + CELL_LO + cc];
    }
    __syncthreads();

    // Build split quad tables (s_c reads stride 27: conflict-free).
    for (int k = tid; k < NCELL_S * TILE; k += THREADS) {
        int cell = k >> 6, d = k & (TILE - 1);
        const float* p = s_c + d * NCOL_S + cell;
        float c0 = p[0], c1 = p[1], c2 = p[2], c3 = p[3];
        float4 a;
        a.x = (c0 + 4.0f * c1 + c2) * (1.0f / 6.0f);
        a.y = (c2 - c0) * 0.5f;
        a.z = (c0 - 2.0f * c1 + c2) * 0.5f;
        a.w = (c3 - c0 + 3.0f * (c1 - c2)) * (1.0f / 6.0f);
        ((d & 1) ? s_o : s_e)[cell * 32 + (d >> 1)] = a;
    }

    const int l    = tid & 31;                 // dim-pair lane
    const int rofs = tid >> 5;                 // 0..7 row within slot
    const int colE = dim0 + 2 * l;
    const int colO = colE + 1;

    float loE = grid[colE * NKNOT], hiE = grid[colE * NKNOT + GRID_NUM];
    float loO = grid[colO * NKNOT], hiO = grid[colO * NKNOT + GRID_NUM];
    const float AE = (float)GRID_NUM / (hiE - loE), BE = fmaf(-loE, AE, -(float)CELL_LO);
    const float AO = (float)GRID_NUM / (hiO - loO), BO = fmaf(-loO, AO, -(float)CELL_LO);

    __syncthreads();

    const float2* __restrict__ x2 = (const float2*)x;
    float2* __restrict__ y2 = (float2*)y;
    const float4* pE = s_e + l;
    const float4* pO = s_o + l;

    const int off     = (dim0 >> 1) + l;
    const int idx0    = (cgrp * 8 + rofs) * (IN_DIM / 2) + off;
    const int SSTEP   = NRGCOL * 8 * (IN_DIM / 2);             // 227328
    const int idx_max = ((NSLOT - 1) * 8 + rofs) * (IN_DIM / 2) + off;

    // Slots 0..7: two MLP=4 batched groups, always in-range
    // (slot index = cgrp + k*111 <= 110 + 7*111 = 887 + ... <= 998 < 1024).
    #pragma unroll
    for (int g = 0; g < 2; ++g) {
        const int base = idx0 + g * 4 * SSTEP;
        float2 xv[4], r[4];
        #pragma unroll
        for (int j = 0; j < 4; ++j)            // 4 LDG.64 in flight
            xv[j] = x2[base + j * SSTEP];
        #pragma unroll
        for (int j = 0; j < 4; ++j) {
            r[j].x = eval_hot(xv[j].x, AE, BE, pE, coef, colE);
            r[j].y = eval_hot(xv[j].y, AO, BO, pO, coef, colO);
        }
        #pragma unroll
        for (int j = 0; j < 4; ++j)
            y2[base + j * SSTEP] = r[j];
    }

    // Tail slots 8,9: slot 8 in-range (<= 998); slot 9 clamped
    // (duplicate rows write identical deterministic values).
    {
        const int i8 = idx0 + 8 * SSTEP;
        const int i9 = min(idx0 + 9 * SSTEP, idx_max);
        float2 xa = x2[i8];
        float2 xb = x2[i9];
        float2 ra, rb;
        ra.x = eval_hot(xa.x, AE, BE, pE, coef, colE);
        ra.y = eval_hot(xa.y, AO, BO, pO, coef, colO);
        rb.x = eval_hot(xb.x, AE, BE, pE, coef, colE);
        rb.y = eval_hot(xb.y, AO, BO, pO, coef, colO);
        y2[i8] = ra;
        y2[i9] = rb;
    }
}

extern "C" void kernel_launch(void* const* d_in, const int* in_sizes, int n_in,
                              void* d_out, int out_size) {
    const float* x    = (const float*)d_in[0];
    const float* grid = (const float*)d_in[1];
    const float* coef = (const float*)d_in[2];
    float* y = (float*)d_out;

    bspline_fused_kernel<<<NBLOCKS, THREADS>>>(x, grid, coef, y);
}